// round 1
// baseline (speedup 1.0000x reference)
#include <cuda_runtime.h>
#include <cstdint>

#define F   16384
#define D   768
#define BSZ 512      // B*S
#define C   16
#define M   (F*C)

#define TI  64       // feature tile in scatter
#define TBS 128      // batch-seq tile in scatter

// Scratch (device globals — no allocations allowed)
__device__ float g_udec_T[(size_t)F * D];     // up_decoder transposed: [F, D]
__device__ float g_ufacts_T[(size_t)F * BSZ]; // up_facts transposed:   [F, BS]
__device__ float g_values[M];

// ---------------------------------------------------------------------------
// Generic 32x32 tiled transpose: src [rows, cols] -> dst [cols, rows]
// ---------------------------------------------------------------------------
__global__ void k_transpose(const float* __restrict__ src, float* __restrict__ dst,
                            int rows, int cols) {
    __shared__ float tile[32][33];
    int x  = blockIdx.x * 32 + threadIdx.x;   // col in src
    int y0 = blockIdx.y * 32 + threadIdx.y;   // row in src
#pragma unroll
    for (int k = 0; k < 32; k += 8)
        tile[threadIdx.y + k][threadIdx.x] = src[(size_t)(y0 + k) * cols + x];
    __syncthreads();
    int x2 = blockIdx.y * 32 + threadIdx.x;   // col in dst (= src row)
    int y2 = blockIdx.x * 32 + threadIdx.y;   // row in dst (= src col)
#pragma unroll
    for (int k = 0; k < 32; k += 8)
        dst[(size_t)(y2 + k) * rows + x2] = tile[threadIdx.x][threadIdx.y + k];
}

// ---------------------------------------------------------------------------
// values[m] = down_encoder[i,:] . up_decoder_T[j,:]   (m = i*C + c)
// One block per feature i (512 threads = 16 warps = C connections).
// Down row cached in smem (reused by all 16 warps); up row gathered
// as 6 independent LDG.128 per lane (contiguous 3KB row, L2-resident).
// ---------------------------------------------------------------------------
__global__ __launch_bounds__(512) void k_values(const float* __restrict__ down_enc,
                                                const int* __restrict__ j_idx) {
    __shared__ float4 sdown[D / 4];           // 768 floats = 192 float4
    int i   = blockIdx.x;
    int tid = threadIdx.x;
    if (tid < D / 4)
        sdown[tid] = reinterpret_cast<const float4*>(down_enc + (size_t)i * D)[tid];
    __syncthreads();

    int warp = tid >> 5, lane = tid & 31;
    int m = i * C + warp;
    int j = j_idx[m];
    const float4* urow = reinterpret_cast<const float4*>(g_udec_T + (size_t)j * D);

    float acc = 0.f;
#pragma unroll
    for (int t = 0; t < 6; t++) {             // 6*32*4 = 768
        float4 u = urow[t * 32 + lane];
        float4 d = sdown[t * 32 + lane];
        acc = fmaf(u.x, d.x, fmaf(u.y, d.y, fmaf(u.z, d.z, fmaf(u.w, d.w, acc))));
    }
#pragma unroll
    for (int o = 16; o; o >>= 1) acc += __shfl_xor_sync(0xffffffffu, acc, o);
    if (lane == 0) g_values[m] = acc;
}

// ---------------------------------------------------------------------------
// Scatter: out[bs, i] = sum_c values[i*C+c] * up_facts_T[j[i*C+c], bs]
// Tile (TI=64 features) x (TBS=128 bs). Each warp owns 8 features; per
// feature, accumulate the 16 connections in a float4 register accumulator
// (lane covers 4 bs), then stage through padded smem to emit fully
// coalesced [bs, F]-layout stores.
// ---------------------------------------------------------------------------
__global__ __launch_bounds__(256) void k_scatter(const int* __restrict__ j_idx,
                                                 float* __restrict__ out) {
    __shared__ float acc[TI][TBS + 4];        // +4 pad keeps float4 alignment
    __shared__ float sval[TI * C];
    __shared__ int   sj[TI * C];

    int i0  = blockIdx.x * TI;
    int bs0 = blockIdx.y * TBS;
    int tid = threadIdx.x;

    for (int idx = tid; idx < TI * C; idx += 256) {
        sval[idx] = g_values[i0 * C + idx];
        sj[idx]   = j_idx[i0 * C + idx];
    }
    __syncthreads();

    int warp = tid >> 5, lane = tid & 31;
#pragma unroll 1
    for (int ii = warp * 8; ii < warp * 8 + 8; ii++) {
        float4 a = make_float4(0.f, 0.f, 0.f, 0.f);
#pragma unroll
        for (int c = 0; c < C; c++) {
            int   j = sj[ii * C + c];
            float v = sval[ii * C + c];
            float4 u = reinterpret_cast<const float4*>(
                           g_ufacts_T + (size_t)j * BSZ + bs0)[lane];
            a.x = fmaf(v, u.x, a.x);
            a.y = fmaf(v, u.y, a.y);
            a.z = fmaf(v, u.z, a.z);
            a.w = fmaf(v, u.w, a.w);
        }
        *reinterpret_cast<float4*>(&acc[ii][lane * 4]) = a;
    }
    __syncthreads();

    // Coalesced stores: consecutive tid -> consecutive feature i
    for (int idx = tid; idx < TI * TBS; idx += 256) {
        int bs = idx >> 6;          // 0..127
        int ii = idx & (TI - 1);    // 0..63
        out[(size_t)(bs0 + bs) * F + i0 + ii] = acc[ii][bs];
    }
}

// ---------------------------------------------------------------------------
extern "C" void kernel_launch(void* const* d_in, const int* in_sizes, int n_in,
                              void* d_out, int out_size) {
    const float* up_facts = (const float*)d_in[0];  // [B,S,F] = [512, 16384]
    const float* down_enc = (const float*)d_in[1];  // [F, D]
    const float* up_dec   = (const float*)d_in[2];  // [D, F]
    const int*   j_idx    = (const int*)d_in[4];    // [M]
    float* out = (float*)d_out;                     // [B,S,F]

    void* p;
    cudaGetSymbolAddress(&p, g_udec_T);
    float* udecT = (float*)p;
    cudaGetSymbolAddress(&p, g_ufacts_T);
    float* ufactsT = (float*)p;

    dim3 tb(32, 8);
    // up_decoder [D, F] -> [F, D]
    k_transpose<<<dim3(F / 32, D / 32), tb>>>(up_dec, udecT, D, F);
    // up_facts [BS, F] -> [F, BS]
    k_transpose<<<dim3(F / 32, BSZ / 32), tb>>>(up_facts, ufactsT, BSZ, F);
    // values
    k_values<<<F, 512>>>(down_enc, j_idx);
    // scatter + output
    k_scatter<<<dim3(F / TI, BSZ / TBS), 256>>>(j_idx, out);
}

// round 2
// speedup vs baseline: 1.1845x; 1.1845x over previous
#include <cuda_runtime.h>
#include <cuda_fp16.h>
#include <cstdint>

#define F   16384
#define D   768
#define BSZ 512      // B*S
#define C   16
#define M   (F*C)

#define TI  64       // feature tile in scatter
#define TBS 128      // batch-seq tile in scatter

// Scratch (device globals — no allocations allowed)
__device__ __half g_udec_h[(size_t)F * D];     // up_decoder transposed, fp16: [F, D]
__device__ __half g_ufacts_h[(size_t)F * BSZ]; // up_facts transposed, fp16:   [F, BS]
__device__ float  g_values[M];

// ---------------------------------------------------------------------------
// 32x32 tiled transpose with fp32 -> fp16 convert: src [rows,cols] -> dst [cols,rows]
// ---------------------------------------------------------------------------
__global__ void k_transpose_h(const float* __restrict__ src, __half* __restrict__ dst,
                              int rows, int cols) {
    __shared__ float tile[32][33];
    int x  = blockIdx.x * 32 + threadIdx.x;
    int y0 = blockIdx.y * 32 + threadIdx.y;
#pragma unroll
    for (int k = 0; k < 32; k += 8)
        tile[threadIdx.y + k][threadIdx.x] = src[(size_t)(y0 + k) * cols + x];
    __syncthreads();
    int x2 = blockIdx.y * 32 + threadIdx.x;
    int y2 = blockIdx.x * 32 + threadIdx.y;
#pragma unroll
    for (int k = 0; k < 32; k += 8)
        dst[(size_t)(y2 + k) * rows + x2] =
            __float2half_rn(tile[threadIdx.x][threadIdx.y + k]);
}

// ---------------------------------------------------------------------------
// values[m] = down_encoder[i,:] . udec_h[j,:]   (m = i*C + c)
// One block per feature i; 16 warps = C connections. Down row (fp32) in smem,
// up row gathered as 3 independent 16B loads/lane (fp16, contiguous 1.5KB row).
// ---------------------------------------------------------------------------
__global__ __launch_bounds__(512) void k_values(const float* __restrict__ down_enc,
                                                const int* __restrict__ j_idx) {
    __shared__ float sdown[D];
    int i   = blockIdx.x;
    int tid = threadIdx.x;
    if (tid < D / 4)
        reinterpret_cast<float4*>(sdown)[tid] =
            reinterpret_cast<const float4*>(down_enc + (size_t)i * D)[tid];
    __syncthreads();

    int warp = tid >> 5, lane = tid & 31;
    int m = i * C + warp;
    int j = j_idx[m];
    const uint4* urow = reinterpret_cast<const uint4*>(g_udec_h + (size_t)j * D);

    float acc = 0.f;
#pragma unroll
    for (int t = 0; t < 3; t++) {            // 3 * 32 lanes * 8 halfs = 768
        uint4 u = urow[t * 32 + lane];
        const float* dp = sdown + (t * 32 + lane) * 8;
        float2 f;
        f = __half22float2(*reinterpret_cast<__half2*>(&u.x));
        acc = fmaf(f.x, dp[0], fmaf(f.y, dp[1], acc));
        f = __half22float2(*reinterpret_cast<__half2*>(&u.y));
        acc = fmaf(f.x, dp[2], fmaf(f.y, dp[3], acc));
        f = __half22float2(*reinterpret_cast<__half2*>(&u.z));
        acc = fmaf(f.x, dp[4], fmaf(f.y, dp[5], acc));
        f = __half22float2(*reinterpret_cast<__half2*>(&u.w));
        acc = fmaf(f.x, dp[6], fmaf(f.y, dp[7], acc));
    }
#pragma unroll
    for (int o = 16; o; o >>= 1) acc += __shfl_xor_sync(0xffffffffu, acc, o);
    if (lane == 0) g_values[m] = acc;
}

// ---------------------------------------------------------------------------
// Scatter: out[bs, i] = sum_c values[i*C+c] * ufacts_h[j[i*C+c], bs]
// Tile TI=64 features x TBS=128 bs. Each warp owns 8 features; lane covers
// 4 bs (one uint2 = 4 fp16 per gather load). fp32 register accumulation,
// staged through padded smem (row stride 129 -> conflict-free final reads)
// for fully coalesced [bs, F] output stores.
// ---------------------------------------------------------------------------
__global__ __launch_bounds__(256) void k_scatter(const int* __restrict__ j_idx,
                                                 float* __restrict__ out) {
    __shared__ float sacc[TI][TBS + 1];
    __shared__ float sval[TI * C];
    __shared__ int   sj[TI * C];

    int i0  = blockIdx.x * TI;
    int bs0 = blockIdx.y * TBS;
    int tid = threadIdx.x;

    for (int idx = tid; idx < TI * C; idx += 256) {
        sval[idx] = g_values[i0 * C + idx];
        sj[idx]   = j_idx[i0 * C + idx];
    }
    __syncthreads();

    int warp = tid >> 5, lane = tid & 31;
#pragma unroll 1
    for (int ii = warp * 8; ii < warp * 8 + 8; ii++) {
        float a0 = 0.f, a1 = 0.f, a2 = 0.f, a3 = 0.f;
#pragma unroll
        for (int c = 0; c < C; c++) {
            int   j = sj[ii * C + c];
            float v = sval[ii * C + c];
            uint2 u = *reinterpret_cast<const uint2*>(
                          g_ufacts_h + (size_t)j * BSZ + bs0 + lane * 4);
            float2 f;
            f = __half22float2(*reinterpret_cast<__half2*>(&u.x));
            a0 = fmaf(v, f.x, a0); a1 = fmaf(v, f.y, a1);
            f = __half22float2(*reinterpret_cast<__half2*>(&u.y));
            a2 = fmaf(v, f.x, a2); a3 = fmaf(v, f.y, a3);
        }
        sacc[ii][lane * 4 + 0] = a0;
        sacc[ii][lane * 4 + 1] = a1;
        sacc[ii][lane * 4 + 2] = a2;
        sacc[ii][lane * 4 + 3] = a3;
    }
    __syncthreads();

    // Coalesced stores: consecutive tid -> consecutive feature i
    for (int idx = tid; idx < TI * TBS; idx += 256) {
        int bs = idx >> 6;          // / TI
        int ii = idx & (TI - 1);
        out[(size_t)(bs0 + bs) * F + i0 + ii] = sacc[ii][bs];
    }
}

// ---------------------------------------------------------------------------
extern "C" void kernel_launch(void* const* d_in, const int* in_sizes, int n_in,
                              void* d_out, int out_size) {
    const float* up_facts = (const float*)d_in[0];  // [B,S,F] = [512, 16384]
    const float* down_enc = (const float*)d_in[1];  // [F, D]
    const float* up_dec   = (const float*)d_in[2];  // [D, F]
    const int*   j_idx    = (const int*)d_in[4];    // [M]
    float* out = (float*)d_out;                     // [B,S,F]

    void* p;
    cudaGetSymbolAddress(&p, g_udec_h);
    __half* udecH = (__half*)p;
    cudaGetSymbolAddress(&p, g_ufacts_h);
    __half* ufactsH = (__half*)p;

    dim3 tb(32, 8);
    // up_decoder [D, F] -> fp16 [F, D]
    k_transpose_h<<<dim3(F / 32, D / 32), tb>>>(up_dec, udecH, D, F);
    // up_facts [BS, F] -> fp16 [F, BS]
    k_transpose_h<<<dim3(F / 32, BSZ / 32), tb>>>(up_facts, ufactsH, BSZ, F);
    // values
    k_values<<<F, 512>>>(down_enc, j_idx);
    // scatter + output
    k_scatter<<<dim3(F / TI, BSZ / TBS), 256>>>(j_idx, out);
}